// round 12
// baseline (speedup 1.0000x reference)
#include <cuda_runtime.h>
#include <cuda_bf16.h>
#include <cstdint>
#include <math.h>

#define NN 4096
#define DD 21
#define BSZ 4
#define QR 48            // 24 hi (21 classes + ones + 2 pad) + 24 lo
#define MT 128           // m rows per block
#define KCB 256          // u8 k-elems per staged chunk (256 B/row)
#define HALFK 2048       // k per block (k-split 2)
#define NCHH (HALFK / KCB)   // 8 chunks
#define NITERS 5
#define THREADS 256

#define A_BYTES (MT * KCB)                // 32768
#define B_BYTES (QR * KCB)                // 12288
#define STAGE_BYTES (A_BYTES + B_BYTES)   // 45056
#define DSMEM_BYTES (2 * STAGE_BYTES)     // 90112

// Static device scratch (no allocation)
__device__ unsigned char g_Wu[(size_t)BSZ * NN * NN];          // 64 MB u8 W
__device__ unsigned char g_QA[BSZ * QR * NN];                  // Q ping (u8 planes)
__device__ unsigned char g_QB[BSZ * QR * NN];                  // Q pong
__device__ int g_part[(size_t)BSZ * 32 * 2 * MT * QR];         // k-split partials (s32)

__device__ __forceinline__ uint32_t smem_u32(const void* p) {
    return (uint32_t)__cvta_generic_to_shared(p);
}
__device__ __forceinline__ void cp16(uint32_t dst, const void* src) {
    asm volatile("cp.async.cg.shared.global [%0], [%1], 16;\n" :: "r"(dst), "l"(src));
}
__device__ __forceinline__ uint32_t lds32(uint32_t a) {
    uint32_t v;
    asm volatile("ld.shared.b32 %0, [%1];" : "=r"(v) : "r"(a));
    return v;
}

// One-time W fp32 -> u8 quantization: round(w*255). Streams 256 MB in, 64 MB out.
__global__ void convertW(const float* __restrict__ W) {
    size_t i = ((size_t)blockIdx.x * 256 + threadIdx.x) * 16;
    uint32_t u[4];
#pragma unroll
    for (int j = 0; j < 4; j++) {
        float4 f = *(const float4*)(W + i + j * 4);
        uint32_t b0 = __float2uint_rn(f.x * 255.f);
        uint32_t b1 = __float2uint_rn(f.y * 255.f);
        uint32_t b2 = __float2uint_rn(f.z * 255.f);
        uint32_t b3 = __float2uint_rn(f.w * 255.f);
        u[j] = b0 | (b1 << 8) | (b2 << 16) | (b3 << 24);
    }
    *(uint4*)(g_Wu + i) = make_uint4(u[0], u[1], u[2], u[3]);
}

// Initial softmax over class dim; 14-bit fixed-point hi/lo u8 planes in BOTH buffers.
__global__ void softmax0_kernel(const float* __restrict__ seg) {
    int idx = blockIdx.x * blockDim.x + threadIdx.x;
    if (idx >= BSZ * NN) return;
    int b = idx >> 12;
    int n = idx & (NN - 1);
    const float* p = seg + (size_t)b * DD * NN + n;
    float v[DD];
    float mx = -3.4e38f;
#pragma unroll
    for (int d = 0; d < DD; d++) { v[d] = p[(size_t)d * NN]; mx = fmaxf(mx, v[d]); }
    float s = 0.f;
#pragma unroll
    for (int d = 0; d < DD; d++) { v[d] = __expf(v[d] - mx); s += v[d]; }
    float si = 1.0f / s;
    unsigned char* qa = g_QA + (size_t)b * QR * NN + n;
    unsigned char* qb = g_QB + (size_t)b * QR * NN + n;
#pragma unroll
    for (int d = 0; d < DD; d++) {
        uint32_t fx = __float2uint_rn(v[d] * si * 16384.f);
        qa[(size_t)d * NN]        = (unsigned char)(fx >> 7);
        qa[(size_t)(24 + d) * NN] = (unsigned char)(fx & 127);
    }
    qa[21 * NN] = 128; qa[22 * NN] = 0; qa[23 * NN] = 0;   // ones-row: v=16384
    qa[45 * NN] = 0;   qa[46 * NN] = 0; qa[47 * NN] = 0;
    qb[21 * NN] = 128; qb[22 * NN] = 0; qb[23 * NN] = 0;
    qb[45 * NN] = 0;   qb[46 * NN] = 0; qb[47 * NN] = 0;
}

// Half-K GEMM (u8 x u8 -> s32, exact): partials[bid][128][48]
__global__ __launch_bounds__(THREADS, 2)
void crf_mma(int qsel)
{
    extern __shared__ char dsm[];
    uint32_t dbase = smem_u32(dsm);

    int tid  = threadIdx.x;
    int wid  = tid >> 5;             // 0..7: warp owns m-rows [wid*16, wid*16+16)
    int lane = tid & 31;
    int tg   = lane >> 2;            // 0..7
    int tig  = lane & 3;             // 0..3
    int bid  = blockIdx.x;
    int b     = bid >> 6;            // 64 blocks per batch (32 mtiles x 2 halves)
    int mtile = (bid & 63) >> 1;
    int h     = bid & 1;
    int m0    = mtile * MT;

    const unsigned char* Qsel = qsel ? g_QB : g_QA;
    const unsigned char* Wbase = g_Wu + ((size_t)(b * NN + m0)) * NN + h * HALFK;
    const unsigned char* Qbase = Qsel + (size_t)b * QR * NN + h * HALFK;

    // stage chunk c into stage buffer st (rows of 256 B, XOR-swizzled 16B granules)
    auto stage = [&](int st, int c) {
        const unsigned char* ws = Wbase + c * KCB;
        uint32_t au = dbase + st * STAGE_BYTES;
#pragma unroll
        for (int i = tid; i < MT * (KCB / 16); i += THREADS) {   // 2048 granules
            int row = i >> 4;
            int g   = i & 15;
            cp16(au + row * 256 + ((g ^ (row & 7)) << 4),
                 ws + (size_t)row * NN + g * 16);
        }
        const unsigned char* qs = Qbase + c * KCB;
        uint32_t bu = dbase + st * STAGE_BYTES + A_BYTES;
#pragma unroll
        for (int i = tid; i < QR * (KCB / 16); i += THREADS) {   // 768 granules
            int row = i >> 4;
            int g   = i & 15;
            cp16(bu + row * 256 + ((g ^ (row & 7)) << 4),
                 qs + (size_t)row * NN + g * 16);
        }
        asm volatile("cp.async.commit_group;\n");
    };

    stage(0, 0);
    stage(1, 1);

    int acc[6][4];
#pragma unroll
    for (int nt = 0; nt < 6; nt++)
#pragma unroll
        for (int j = 0; j < 4; j++) acc[nt][j] = 0;

    for (int c = 0; c < NCHH; c++) {
        if (c < NCHH - 1) asm volatile("cp.async.wait_group 1;\n" ::: "memory");
        else              asm volatile("cp.async.wait_group 0;\n" ::: "memory");
        __syncthreads();

        uint32_t Ab = dbase + (c & 1) * STAGE_BYTES;
        uint32_t Bq = Ab + A_BYTES;
        uint32_t rowa = (uint32_t)(wid * 16 + tg);
        uint32_t ra = Ab + rowa * 256 + 4 * tig;
        uint32_t rb = ra + 8 * 256;

#pragma unroll
        for (int s = 0; s < KCB / 32; s++) {          // 8 k-steps of 32
            uint32_t sw0 = (uint32_t)(((2 * s)     ^ tg) << 4);
            uint32_t sw1 = (uint32_t)(((2 * s + 1) ^ tg) << 4);
            uint32_t a0 = lds32(ra + sw0);
            uint32_t a2 = lds32(ra + sw1);
            uint32_t a1 = lds32(rb + sw0);
            uint32_t a3 = lds32(rb + sw1);
#pragma unroll
            for (int nt = 0; nt < 6; nt++) {
                uint32_t db = Bq + (uint32_t)(nt * 8 + tg) * 256 + 4 * tig;
                uint32_t b0 = lds32(db + sw0);
                uint32_t b1 = lds32(db + sw1);
                asm volatile(
                    "mma.sync.aligned.m16n8k32.row.col.s32.u8.u8.s32 "
                    "{%0,%1,%2,%3}, {%4,%5,%6,%7}, {%8,%9}, {%0,%1,%2,%3};"
                    : "+r"(acc[nt][0]), "+r"(acc[nt][1]),
                      "+r"(acc[nt][2]), "+r"(acc[nt][3])
                    : "r"(a0), "r"(a1), "r"(a2), "r"(a3),
                      "r"(b0), "r"(b1));
            }
        }
        __syncthreads();
        if (c + 2 < NCHH) stage(c & 1, c + 2);
    }

    // write partials (s32, deterministic; merged by crf_ep)
    int* pb = g_part + (size_t)bid * MT * QR;
    int r = wid * 16 + tg;
#pragma unroll
    for (int nt = 0; nt < 6; nt++) {
        int col = nt * 8 + 2 * tig;
        *(int2*)(pb + (size_t)r * QR + col)       = make_int2(acc[nt][0], acc[nt][1]);
        *(int2*)(pb + (size_t)(r + 8) * QR + col) = make_int2(acc[nt][2], acc[nt][3]);
    }
}

// Merge k-split partials + fused epilogue (coalesced int4 loads through smem).
__global__ __launch_bounds__(256)
void crf_ep(const float* __restrict__ seg,
            const float* __restrict__ wts,
            float* __restrict__ out,
            int qsel, int last)
{
    __shared__ float w_s[DD * DD];
    __shared__ float sp[MT][QR + 1];     // pitch 49: conflict-free row reads
    int tid = threadIdx.x;
    int bid = blockIdx.x;            // BSZ*32 blocks
    int b = bid >> 5;
    int mtile = bid & 31;
    for (int i = tid; i < DD * DD; i += 256) w_s[i] = wts[i];

    const int* pb = g_part + (size_t)(bid * 2) * MT * QR;
#pragma unroll
    for (int i = tid; i < MT * QR / 4; i += 256) {    // 1536 int4s
        int4 v0 = *(const int4*)(pb + (size_t)i * 4);
        int4 v1 = *(const int4*)(pb + (size_t)MT * QR + (size_t)i * 4);
        int r = (i * 4) / QR;
        int c = (i * 4) % QR;                          // QR%4==0: same row
        sp[r][c]     = (float)(v0.x + v1.x);
        sp[r][c + 1] = (float)(v0.y + v1.y);
        sp[r][c + 2] = (float)(v0.z + v1.z);
        sp[r][c + 3] = (float)(v0.w + v1.w);
    }
    __syncthreads();

    if (tid < MT) {
        int m = mtile * MT + tid;
        float a2[DD + 1];
#pragma unroll
        for (int d = 0; d <= DD; d++)
            a2[d] = sp[tid][d] * 128.f + sp[tid][24 + d];   // hi*128 + lo (exact)

        float rinv = 1.0f / a2[DD];       // rowsum via ones-row (col 21); scales cancel
        float sd[DD];
#pragma unroll
        for (int e = 0; e < DD; e++) sd[e] = a2[e] * rinv;

        float o[DD];
#pragma unroll
        for (int d = 0; d < DD; d++) {
            float u = 0.f;
#pragma unroll
            for (int e = 0; e < DD; e++) u = fmaf(w_s[d * DD + e], sd[e], u);
            o[d] = seg[((size_t)(b * DD + d)) * NN + m] - u;
        }

        if (last) {
#pragma unroll
            for (int d = 0; d < DD; d++)
                out[((size_t)(b * DD + d)) * NN + m] = o[d];
        } else {
            float mx = -3.4e38f;
#pragma unroll
            for (int d = 0; d < DD; d++) mx = fmaxf(mx, o[d]);
            float ssum = 0.f;
            float ex[DD];
#pragma unroll
            for (int d = 0; d < DD; d++) { ex[d] = __expf(o[d] - mx); ssum += ex[d]; }
            float si = 1.0f / ssum;
            unsigned char* qo = (qsel ? g_QA : g_QB) + (size_t)b * QR * NN + m;
#pragma unroll
            for (int d = 0; d < DD; d++) {
                uint32_t fx = __float2uint_rn(ex[d] * si * 16384.f);
                qo[(size_t)d * NN]        = (unsigned char)(fx >> 7);
                qo[(size_t)(24 + d) * NN] = (unsigned char)(fx & 127);
            }
        }
    }
}

extern "C" void kernel_launch(void* const* d_in, const int* in_sizes, int n_in,
                              void* d_out, int out_size)
{
    const float* seg = nullptr;
    const float* W   = nullptr;
    const float* wts = nullptr;
    for (int i = 0; i < n_in; i++) {
        if (in_sizes[i] == BSZ * DD * NN)       seg = (const float*)d_in[i];
        else if (in_sizes[i] == BSZ * NN * NN)  W   = (const float*)d_in[i];
        else if (in_sizes[i] == DD * DD)        wts = (const float*)d_in[i];
    }

    cudaFuncSetAttribute(crf_mma, cudaFuncAttributeMaxDynamicSharedMemorySize,
                         DSMEM_BYTES);

    convertW<<<16384, 256>>>(W);                       // 64M elems / (256*16)
    softmax0_kernel<<<(BSZ * NN) / 256, 256>>>(seg);
    for (int it = 0; it < NITERS; it++) {
        crf_mma<<<BSZ * 64, THREADS, DSMEM_BYTES>>>(it & 1);
        crf_ep<<<BSZ * 32, 256>>>(seg, wts, (float*)d_out,
                                  it & 1, (it == NITERS - 1) ? 1 : 0);
    }
}

// round 13
// speedup vs baseline: 1.4639x; 1.4639x over previous
#include <cuda_runtime.h>
#include <cuda_bf16.h>
#include <cstdint>
#include <math.h>

#define NN 4096
#define DD 21
#define BSZ 4
#define QR 48            // 24 hi (21 classes + ones + 2 pad) + 24 lo
#define MT 128           // m rows per block
#define KCB 128          // bf16 k per staged chunk
#define HALFK 2048       // k per block (k-split 2)
#define NCHH (HALFK / KCB)   // 16 chunks
#define NITERS 5
#define THREADS 256

#define A_BYTES (MT * KCB * 2)            // 32768
#define B_BYTES (QR * KCB * 2)            // 12288
#define STAGE_BYTES (A_BYTES + B_BYTES)   // 45056
#define DSMEM_BYTES (2 * STAGE_BYTES)     // 90112
#define W0_DSMEM (A_BYTES + 2 * B_BYTES)  // 57344

// Static device scratch (no allocation)
__device__ __nv_bfloat16 g_Wb[(size_t)BSZ * NN * NN];          // 128 MB bf16 W
__device__ __nv_bfloat16 g_QA[BSZ * QR * NN];                  // Q ping
__device__ __nv_bfloat16 g_QB[BSZ * QR * NN];                  // Q pong
__device__ float g_part[(size_t)BSZ * 32 * 2 * MT * QR];       // k-split partials

__device__ __forceinline__ uint32_t smem_u32(const void* p) {
    return (uint32_t)__cvta_generic_to_shared(p);
}
__device__ __forceinline__ void cp16(uint32_t dst, const void* src) {
    asm volatile("cp.async.cg.shared.global [%0], [%1], 16;\n" :: "r"(dst), "l"(src));
}
__device__ __forceinline__ uint32_t lds32(uint32_t a) {
    uint32_t v;
    asm volatile("ld.shared.b32 %0, [%1];" : "=r"(v) : "r"(a));
    return v;
}
__device__ __forceinline__ uint32_t bfbits(__nv_bfloat162 p) {
    return *(uint32_t*)&p;
}

// Initial softmax over class dim; bf16 hi/lo split + ones/pad rows in BOTH buffers.
__global__ void softmax0_kernel(const float* __restrict__ seg) {
    int idx = blockIdx.x * blockDim.x + threadIdx.x;
    if (idx >= BSZ * NN) return;
    int b = idx >> 12;
    int n = idx & (NN - 1);
    const float* p = seg + (size_t)b * DD * NN + n;
    float v[DD];
    float mx = -3.4e38f;
#pragma unroll
    for (int d = 0; d < DD; d++) { v[d] = p[(size_t)d * NN]; mx = fmaxf(mx, v[d]); }
    float s = 0.f;
#pragma unroll
    for (int d = 0; d < DD; d++) { v[d] = __expf(v[d] - mx); s += v[d]; }
    float si = 1.0f / s;
    __nv_bfloat16* qa = g_QA + (size_t)b * QR * NN + n;
    __nv_bfloat16* qb = g_QB + (size_t)b * QR * NN + n;
#pragma unroll
    for (int d = 0; d < DD; d++) {
        float q = v[d] * si;
        __nv_bfloat16 h = __float2bfloat16(q);
        qa[(size_t)d * NN] = h;
        qa[(size_t)(24 + d) * NN] = __float2bfloat16(q - __bfloat162float(h));
    }
    __nv_bfloat16 one = __float2bfloat16(1.0f);
    __nv_bfloat16 zer = __float2bfloat16(0.0f);
    qa[21 * NN] = one; qa[22 * NN] = zer; qa[23 * NN] = zer;
    qa[45 * NN] = zer; qa[46 * NN] = zer; qa[47 * NN] = zer;
    qb[21 * NN] = one; qb[22 * NN] = zer; qb[23 * NN] = zer;
    qb[45 * NN] = zer; qb[46 * NN] = zer; qb[47 * NN] = zer;
}

// Shared MMA inner step (identical fragment addressing in both kernels)
#define MMA_CHUNK(Ab, Bq)                                                        \
    {                                                                            \
        uint32_t rowa = (uint32_t)(wid * 16 + tg);                               \
        uint32_t ra = (Ab) + rowa * 256 + 4 * tig;                               \
        uint32_t rb = ra + 8 * 256;                                              \
        _Pragma("unroll")                                                        \
        for (int s = 0; s < KCB / 16; s++) {                                     \
            uint32_t sw0 = (uint32_t)(((2 * s)     ^ tg) << 4);                  \
            uint32_t sw1 = (uint32_t)(((2 * s + 1) ^ tg) << 4);                  \
            uint32_t a0 = lds32(ra + sw0);                                       \
            uint32_t a2 = lds32(ra + sw1);                                       \
            uint32_t a1 = lds32(rb + sw0);                                       \
            uint32_t a3 = lds32(rb + sw1);                                       \
            _Pragma("unroll")                                                    \
            for (int nt = 0; nt < 6; nt++) {                                     \
                uint32_t db = (Bq) + (uint32_t)(nt * 8 + tg) * 256 + 4 * tig;    \
                uint32_t b0 = lds32(db + sw0);                                   \
                uint32_t b1 = lds32(db + sw1);                                   \
                asm volatile(                                                    \
                    "mma.sync.aligned.m16n8k16.row.col.f32.bf16.bf16.f32 "       \
                    "{%0,%1,%2,%3}, {%4,%5,%6,%7}, {%8,%9}, {%0,%1,%2,%3};"      \
                    : "+f"(acc[nt][0]), "+f"(acc[nt][1]),                        \
                      "+f"(acc[nt][2]), "+f"(acc[nt][3])                         \
                    : "r"(a0), "r"(a1), "r"(a2), "r"(a3),                        \
                      "r"(b0), "r"(b1));                                         \
            }                                                                    \
        }                                                                        \
    }

#define WRITE_PARTIALS()                                                         \
    {                                                                            \
        float* pb = g_part + (size_t)bid * MT * QR;                              \
        int r = wid * 16 + tg;                                                   \
        _Pragma("unroll")                                                        \
        for (int nt = 0; nt < 6; nt++) {                                         \
            int col = nt * 8 + 2 * tig;                                          \
            *(float2*)(pb + (size_t)r * QR + col) =                              \
                make_float2(acc[nt][0], acc[nt][1]);                             \
            *(float2*)(pb + (size_t)(r + 8) * QR + col) =                        \
                make_float2(acc[nt][2], acc[nt][3]);                             \
        }                                                                        \
    }

// Iteration 0: fused W fp32->bf16 convert + half-K GEMM. A staged via
// LDG.128 -> register convert -> STS (swizzled) + STG to g_Wb.
__global__ __launch_bounds__(THREADS, 2)
void crf_mma_w0(const float* __restrict__ W)
{
    extern __shared__ char dsm[];
    uint32_t dbase = smem_u32(dsm);      // A: 32 KB, then B0, B1 (12 KB each)
    uint32_t Abuf = dbase;
    uint32_t Bbuf0 = dbase + A_BYTES;

    int tid  = threadIdx.x;
    int wid  = tid >> 5;
    int lane = tid & 31;
    int tg   = lane >> 2;
    int tig  = lane & 3;
    int bid  = blockIdx.x;
    int b     = bid >> 6;
    int mtile = (bid & 63) >> 1;
    int h     = bid & 1;
    int m0    = mtile * MT;

    const float* WbaseF = W + ((size_t)(b * NN + m0)) * NN + h * HALFK;
    __nv_bfloat16* WbOut = g_Wb + ((size_t)(b * NN + m0)) * NN + h * HALFK;
    const __nv_bfloat16* Qbase = g_QA + (size_t)b * QR * NN + h * HALFK;

    auto stageB = [&](int st, int c) {
        const __nv_bfloat16* qs = Qbase + c * KCB;
        uint32_t bu = Bbuf0 + st * B_BYTES;
#pragma unroll
        for (int i = tid; i < QR * (KCB / 8); i += THREADS) {
            int row = i >> 4;
            int g   = i & 15;
            cp16(bu + row * 256 + ((g ^ (row & 7)) << 4),
                 qs + (size_t)row * NN + g * 8);
        }
        asm volatile("cp.async.commit_group;\n");
    };

    stageB(0, 0);
    stageB(1, 1);

    float acc[6][4];
#pragma unroll
    for (int nt = 0; nt < 6; nt++)
#pragma unroll
        for (int j = 0; j < 4; j++) acc[nt][j] = 0.f;

    for (int c = 0; c < NCHH; c++) {
        // stage A chunk c: fp32 LDG -> bf16 -> STS + STG (16B bf16 granules)
#pragma unroll
        for (int i = tid; i < MT * (KCB / 8); i += THREADS) {   // 2048 granules
            int row = i >> 4;
            int g   = i & 15;
            const float* srcF = WbaseF + (size_t)row * NN + c * KCB + g * 8;
            float4 f0 = *(const float4*)srcF;
            float4 f1 = *(const float4*)(srcF + 4);
            uint4 u;
            u.x = bfbits(__float22bfloat162_rn(make_float2(f0.x, f0.y)));
            u.y = bfbits(__float22bfloat162_rn(make_float2(f0.z, f0.w)));
            u.z = bfbits(__float22bfloat162_rn(make_float2(f1.x, f1.y)));
            u.w = bfbits(__float22bfloat162_rn(make_float2(f1.z, f1.w)));
            *(uint4*)(dsm + (A_BYTES * 0) + row * 256 + ((g ^ (row & 7)) << 4)) = u;
            *(uint4*)(WbOut + (size_t)row * NN + c * KCB + g * 8) = u;
        }

        if (c < NCHH - 1) asm volatile("cp.async.wait_group 1;\n" ::: "memory");
        else              asm volatile("cp.async.wait_group 0;\n" ::: "memory");
        __syncthreads();

        MMA_CHUNK(Abuf, Bbuf0 + (uint32_t)((c & 1) * B_BYTES));

        __syncthreads();
        if (c + 2 < NCHH) stageB(c & 1, c + 2);
    }

    WRITE_PARTIALS();
}

// Iterations 1..4: half-K GEMM on pre-converted bf16 W (round-11 proven kernel).
__global__ __launch_bounds__(THREADS, 2)
void crf_mma(int qsel)
{
    extern __shared__ char dsm[];
    uint32_t dbase = smem_u32(dsm);

    int tid  = threadIdx.x;
    int wid  = tid >> 5;
    int lane = tid & 31;
    int tg   = lane >> 2;
    int tig  = lane & 3;
    int bid  = blockIdx.x;
    int b     = bid >> 6;
    int mtile = (bid & 63) >> 1;
    int h     = bid & 1;
    int m0    = mtile * MT;

    const __nv_bfloat16* Qsel = qsel ? g_QB : g_QA;
    const __nv_bfloat16* Wbase = g_Wb + ((size_t)(b * NN + m0)) * NN + h * HALFK;
    const __nv_bfloat16* Qbase = Qsel + (size_t)b * QR * NN + h * HALFK;

    auto stage = [&](int st, int c) {
        const __nv_bfloat16* ws = Wbase + c * KCB;
        uint32_t au = dbase + st * STAGE_BYTES;
#pragma unroll
        for (int i = tid; i < MT * (KCB / 8); i += THREADS) {
            int row = i >> 4;
            int g   = i & 15;
            cp16(au + row * 256 + ((g ^ (row & 7)) << 4),
                 ws + (size_t)row * NN + g * 8);
        }
        const __nv_bfloat16* qs = Qbase + c * KCB;
        uint32_t bu = dbase + st * STAGE_BYTES + A_BYTES;
#pragma unroll
        for (int i = tid; i < QR * (KCB / 8); i += THREADS) {
            int row = i >> 4;
            int g   = i & 15;
            cp16(bu + row * 256 + ((g ^ (row & 7)) << 4),
                 qs + (size_t)row * NN + g * 8);
        }
        asm volatile("cp.async.commit_group;\n");
    };

    stage(0, 0);
    stage(1, 1);

    float acc[6][4];
#pragma unroll
    for (int nt = 0; nt < 6; nt++)
#pragma unroll
        for (int j = 0; j < 4; j++) acc[nt][j] = 0.f;

    for (int c = 0; c < NCHH; c++) {
        if (c < NCHH - 1) asm volatile("cp.async.wait_group 1;\n" ::: "memory");
        else              asm volatile("cp.async.wait_group 0;\n" ::: "memory");
        __syncthreads();

        uint32_t Ab = dbase + (c & 1) * STAGE_BYTES;
        MMA_CHUNK(Ab, Ab + A_BYTES);

        __syncthreads();
        if (c + 2 < NCHH) stage(c & 1, c + 2);
    }

    WRITE_PARTIALS();
}

// Merge k-split partials + fused epilogue (coalesced float4 loads through smem).
__global__ __launch_bounds__(256)
void crf_ep(const float* __restrict__ seg,
            const float* __restrict__ wts,
            float* __restrict__ out,
            int qsel, int last)
{
    __shared__ float w_s[DD * DD];
    __shared__ float sp[MT][QR + 1];
    int tid = threadIdx.x;
    int bid = blockIdx.x;
    int b = bid >> 5;
    int mtile = bid & 31;
    for (int i = tid; i < DD * DD; i += 256) w_s[i] = wts[i];

    const float* pb = g_part + (size_t)(bid * 2) * MT * QR;
#pragma unroll
    for (int i = tid; i < MT * QR / 4; i += 256) {
        float4 v0 = *(const float4*)(pb + (size_t)i * 4);
        float4 v1 = *(const float4*)(pb + (size_t)MT * QR + (size_t)i * 4);
        int r = (i * 4) / QR;
        int c = (i * 4) % QR;
        sp[r][c]     = v0.x + v1.x;
        sp[r][c + 1] = v0.y + v1.y;
        sp[r][c + 2] = v0.z + v1.z;
        sp[r][c + 3] = v0.w + v1.w;
    }
    __syncthreads();

    if (tid < MT) {
        int m = mtile * MT + tid;
        float a2[DD + 1];
#pragma unroll
        for (int d = 0; d <= DD; d++) a2[d] = sp[tid][d] + sp[tid][24 + d];

        float rinv = 1.0f / a2[DD];
        float sd[DD];
#pragma unroll
        for (int e = 0; e < DD; e++) sd[e] = a2[e] * rinv;

        float o[DD];
#pragma unroll
        for (int d = 0; d < DD; d++) {
            float u = 0.f;
#pragma unroll
            for (int e = 0; e < DD; e++) u = fmaf(w_s[d * DD + e], sd[e], u);
            o[d] = seg[((size_t)(b * DD + d)) * NN + m] - u;
        }

        if (last) {
#pragma unroll
            for (int d = 0; d < DD; d++)
                out[((size_t)(b * DD + d)) * NN + m] = o[d];
        } else {
            float mx = -3.4e38f;
#pragma unroll
            for (int d = 0; d < DD; d++) mx = fmaxf(mx, o[d]);
            float ssum = 0.f;
            float ex[DD];
#pragma unroll
            for (int d = 0; d < DD; d++) { ex[d] = __expf(o[d] - mx); ssum += ex[d]; }
            float si = 1.0f / ssum;
            __nv_bfloat16* qo = (qsel ? g_QA : g_QB) + (size_t)b * QR * NN + m;
#pragma unroll
            for (int d = 0; d < DD; d++) {
                float q = ex[d] * si;
                __nv_bfloat16 hb = __float2bfloat16(q);
                qo[(size_t)d * NN] = hb;
                qo[(size_t)(24 + d) * NN] = __float2bfloat16(q - __bfloat162float(hb));
            }
        }
    }
}

extern "C" void kernel_launch(void* const* d_in, const int* in_sizes, int n_in,
                              void* d_out, int out_size)
{
    const float* seg = nullptr;
    const float* W   = nullptr;
    const float* wts = nullptr;
    for (int i = 0; i < n_in; i++) {
        if (in_sizes[i] == BSZ * DD * NN)       seg = (const float*)d_in[i];
        else if (in_sizes[i] == BSZ * NN * NN)  W   = (const float*)d_in[i];
        else if (in_sizes[i] == DD * DD)        wts = (const float*)d_in[i];
    }

    cudaFuncSetAttribute(crf_mma, cudaFuncAttributeMaxDynamicSharedMemorySize,
                         DSMEM_BYTES);
    cudaFuncSetAttribute(crf_mma_w0, cudaFuncAttributeMaxDynamicSharedMemorySize,
                         W0_DSMEM);

    softmax0_kernel<<<(BSZ * NN) / 256, 256>>>(seg);
    for (int it = 0; it < NITERS; it++) {
        if (it == 0)
            crf_mma_w0<<<BSZ * 64, THREADS, W0_DSMEM>>>(W);
        else
            crf_mma<<<BSZ * 64, THREADS, DSMEM_BYTES>>>(it & 1);
        crf_ep<<<BSZ * 32, 256>>>(seg, wts, (float*)d_out,
                                  it & 1, (it == NITERS - 1) ? 1 : 0);
    }
}

// round 14
// speedup vs baseline: 1.4663x; 1.0016x over previous
#include <cuda_runtime.h>
#include <cuda_bf16.h>
#include <cstdint>
#include <math.h>

#define NN 4096
#define DD 21
#define BSZ 4
#define QR 48            // 24 hi (21 classes + ones + 2 pad) + 24 lo
#define MT 128           // m rows per block
#define KCB 128          // bf16 k per staged chunk
#define HALFK 2048       // k per block (k-split 2)
#define NCHH (HALFK / KCB)   // 16 chunks
#define NITERS 5
#define THREADS 256

#define A_BYTES (MT * KCB * 2)            // 32768
#define B_BYTES (QR * KCB * 2)            // 12288
#define STAGE_BYTES (A_BYTES + B_BYTES)   // 45056
#define DSMEM_BYTES (2 * STAGE_BYTES)     // 90112
#define W0_DSMEM (A_BYTES + 2 * B_BYTES)  // 57344

// Static device scratch (no allocation)
__device__ __nv_bfloat16 g_Wb[(size_t)BSZ * NN * NN];          // 128 MB bf16 W
__device__ __nv_bfloat16 g_QA[BSZ * QR * NN];                  // Q ping
__device__ __nv_bfloat16 g_QB[BSZ * QR * NN];                  // Q pong
__device__ float g_part[(size_t)BSZ * 32 * 2 * MT * QR];       // k-split partials

__device__ __forceinline__ uint32_t smem_u32(const void* p) {
    return (uint32_t)__cvta_generic_to_shared(p);
}
__device__ __forceinline__ void cp16(uint32_t dst, const void* src) {
    asm volatile("cp.async.cg.shared.global [%0], [%1], 16;\n" :: "r"(dst), "l"(src));
}
__device__ __forceinline__ uint32_t lds32(uint32_t a) {
    uint32_t v;
    asm volatile("ld.shared.b32 %0, [%1];" : "=r"(v) : "r"(a));
    return v;
}
__device__ __forceinline__ uint32_t bfbits(__nv_bfloat162 p) {
    return *(uint32_t*)&p;
}

// Initial softmax over class dim; bf16 hi/lo split + ones/pad rows in BOTH buffers.
__global__ void softmax0_kernel(const float* __restrict__ seg) {
    int idx = blockIdx.x * blockDim.x + threadIdx.x;
    if (idx >= BSZ * NN) return;
    int b = idx >> 12;
    int n = idx & (NN - 1);
    const float* p = seg + (size_t)b * DD * NN + n;
    float v[DD];
    float mx = -3.4e38f;
#pragma unroll
    for (int d = 0; d < DD; d++) { v[d] = p[(size_t)d * NN]; mx = fmaxf(mx, v[d]); }
    float s = 0.f;
#pragma unroll
    for (int d = 0; d < DD; d++) { v[d] = __expf(v[d] - mx); s += v[d]; }
    float si = 1.0f / s;
    __nv_bfloat16* qa = g_QA + (size_t)b * QR * NN + n;
    __nv_bfloat16* qb = g_QB + (size_t)b * QR * NN + n;
#pragma unroll
    for (int d = 0; d < DD; d++) {
        float q = v[d] * si;
        __nv_bfloat16 h = __float2bfloat16(q);
        qa[(size_t)d * NN] = h;
        qa[(size_t)(24 + d) * NN] = __float2bfloat16(q - __bfloat162float(h));
    }
    __nv_bfloat16 one = __float2bfloat16(1.0f);
    __nv_bfloat16 zer = __float2bfloat16(0.0f);
    qa[21 * NN] = one; qa[22 * NN] = zer; qa[23 * NN] = zer;
    qa[45 * NN] = zer; qa[46 * NN] = zer; qa[47 * NN] = zer;
    qb[21 * NN] = one; qb[22 * NN] = zer; qb[23 * NN] = zer;
    qb[45 * NN] = zer; qb[46 * NN] = zer; qb[47 * NN] = zer;
}

// Iteration 0: fused W fp32->bf16 convert + half-K GEMM. A staged via
// LDG.128 -> register convert -> STS (swizzled) + STG to g_Wb.
__global__ __launch_bounds__(THREADS, 2)
void crf_mma_w0(const float* __restrict__ W)
{
    extern __shared__ char dsm[];
    uint32_t dbase = smem_u32(dsm);      // A: 32 KB, then B0, B1 (12 KB each)
    uint32_t Abuf = dbase;
    uint32_t Bbuf0 = dbase + A_BYTES;

    int tid  = threadIdx.x;
    int wid  = tid >> 5;
    int lane = tid & 31;
    int tg   = lane >> 2;
    int tig  = lane & 3;
    int bid  = blockIdx.x;
    int b     = bid >> 6;
    int mtile = (bid & 63) >> 1;
    int h     = bid & 1;
    int m0    = mtile * MT;

    const float* WbaseF = W + ((size_t)(b * NN + m0)) * NN + h * HALFK;
    __nv_bfloat16* WbOut = g_Wb + ((size_t)(b * NN + m0)) * NN + h * HALFK;
    const __nv_bfloat16* Qbase = g_QA + (size_t)b * QR * NN + h * HALFK;

    auto stageB = [&](int st, int c) {
        const __nv_bfloat16* qs = Qbase + c * KCB;
        uint32_t bu = Bbuf0 + st * B_BYTES;
#pragma unroll
        for (int i = tid; i < QR * (KCB / 8); i += THREADS) {
            int row = i >> 4;
            int g   = i & 15;
            cp16(bu + row * 256 + ((g ^ (row & 7)) << 4),
                 qs + (size_t)row * NN + g * 8);
        }
        asm volatile("cp.async.commit_group;\n");
    };

    stageB(0, 0);
    stageB(1, 1);

    float acc[6][4];
#pragma unroll
    for (int nt = 0; nt < 6; nt++)
#pragma unroll
        for (int j = 0; j < 4; j++) acc[nt][j] = 0.f;

    for (int c = 0; c < NCHH; c++) {
        // stage A chunk c: fp32 LDG -> bf16 -> STS + STG (16B bf16 granules)
#pragma unroll
        for (int i = tid; i < MT * (KCB / 8); i += THREADS) {   // 2048 granules
            int row = i >> 4;
            int g   = i & 15;
            const float* srcF = WbaseF + (size_t)row * NN + c * KCB + g * 8;
            float4 f0 = *(const float4*)srcF;
            float4 f1 = *(const float4*)(srcF + 4);
            uint4 u;
            u.x = bfbits(__float22bfloat162_rn(make_float2(f0.x, f0.y)));
            u.y = bfbits(__float22bfloat162_rn(make_float2(f0.z, f0.w)));
            u.z = bfbits(__float22bfloat162_rn(make_float2(f1.x, f1.y)));
            u.w = bfbits(__float22bfloat162_rn(make_float2(f1.z, f1.w)));
            *(uint4*)(dsm + row * 256 + ((g ^ (row & 7)) << 4)) = u;
            *(uint4*)(WbOut + (size_t)row * NN + c * KCB + g * 8) = u;
        }

        if (c < NCHH - 1) asm volatile("cp.async.wait_group 1;\n" ::: "memory");
        else              asm volatile("cp.async.wait_group 0;\n" ::: "memory");
        __syncthreads();

        uint32_t Bq = Bbuf0 + (uint32_t)((c & 1) * B_BYTES);
        uint32_t rowa = (uint32_t)(wid * 16 + tg);
        uint32_t ra = Abuf + rowa * 256 + 4 * tig;
        uint32_t rb = ra + 8 * 256;

#pragma unroll
        for (int s = 0; s < KCB / 16; s++) {          // 8 k-steps of 16
            uint32_t sw0 = (uint32_t)(((2 * s)     ^ tg) << 4);
            uint32_t sw1 = (uint32_t)(((2 * s + 1) ^ tg) << 4);
            uint32_t a0 = lds32(ra + sw0);
            uint32_t a2 = lds32(ra + sw1);
            uint32_t a1 = lds32(rb + sw0);
            uint32_t a3 = lds32(rb + sw1);
#pragma unroll
            for (int nt = 0; nt < 6; nt++) {
                uint32_t db = Bq + (uint32_t)(nt * 8 + tg) * 256 + 4 * tig;
                uint32_t b0 = lds32(db + sw0);
                uint32_t b1 = lds32(db + sw1);
                asm volatile(
                    "mma.sync.aligned.m16n8k16.row.col.f32.bf16.bf16.f32 "
                    "{%0,%1,%2,%3}, {%4,%5,%6,%7}, {%8,%9}, {%0,%1,%2,%3};"
                    : "+f"(acc[nt][0]), "+f"(acc[nt][1]),
                      "+f"(acc[nt][2]), "+f"(acc[nt][3])
                    : "r"(a0), "r"(a1), "r"(a2), "r"(a3),
                      "r"(b0), "r"(b1));
            }
        }
        __syncthreads();
        if (c + 2 < NCHH) stageB(c & 1, c + 2);
    }

    float* pb = g_part + (size_t)bid * MT * QR;
    int r = wid * 16 + tg;
#pragma unroll
    for (int nt = 0; nt < 6; nt++) {
        int col = nt * 8 + 2 * tig;
        *(float2*)(pb + (size_t)r * QR + col)       = make_float2(acc[nt][0], acc[nt][1]);
        *(float2*)(pb + (size_t)(r + 8) * QR + col) = make_float2(acc[nt][2], acc[nt][3]);
    }
}

// Iterations 1..4: half-K GEMM on bf16 W — round-11 proven kernel, verbatim.
__global__ __launch_bounds__(THREADS, 2)
void crf_mma(int qsel)
{
    extern __shared__ char dsm[];
    uint32_t dbase = smem_u32(dsm);

    int tid  = threadIdx.x;
    int wid  = tid >> 5;             // 0..7: warp owns m-rows [wid*16, wid*16+16)
    int lane = tid & 31;
    int tg   = lane >> 2;            // 0..7
    int tig  = lane & 3;             // 0..3
    int bid  = blockIdx.x;
    int b     = bid >> 6;            // 64 blocks per batch (32 mtiles x 2 halves)
    int mtile = (bid & 63) >> 1;
    int h     = bid & 1;
    int m0    = mtile * MT;

    const __nv_bfloat16* Qsel = qsel ? g_QB : g_QA;
    const __nv_bfloat16* Wbase = g_Wb + ((size_t)(b * NN + m0)) * NN + h * HALFK;
    const __nv_bfloat16* Qbase = Qsel + (size_t)b * QR * NN + h * HALFK;

    // stage chunk c into stage buffer st
    auto stage = [&](int st, int c) {
        const __nv_bfloat16* ws = Wbase + c * KCB;
        uint32_t au = dbase + st * STAGE_BYTES;
#pragma unroll
        for (int i = tid; i < MT * (KCB / 8); i += THREADS) {   // 2048 granules
            int row = i >> 4;
            int g   = i & 15;
            cp16(au + row * 256 + ((g ^ (row & 7)) << 4),
                 ws + (size_t)row * NN + g * 8);
        }
        const __nv_bfloat16* qs = Qbase + c * KCB;
        uint32_t bu = dbase + st * STAGE_BYTES + A_BYTES;
#pragma unroll
        for (int i = tid; i < QR * (KCB / 8); i += THREADS) {   // 768 granules
            int row = i >> 4;
            int g   = i & 15;
            cp16(bu + row * 256 + ((g ^ (row & 7)) << 4),
                 qs + (size_t)row * NN + g * 8);
        }
        asm volatile("cp.async.commit_group;\n");
    };

    stage(0, 0);
    stage(1, 1);

    float acc[6][4];
#pragma unroll
    for (int nt = 0; nt < 6; nt++)
#pragma unroll
        for (int j = 0; j < 4; j++) acc[nt][j] = 0.f;

    for (int c = 0; c < NCHH; c++) {
        if (c < NCHH - 1) asm volatile("cp.async.wait_group 1;\n" ::: "memory");
        else              asm volatile("cp.async.wait_group 0;\n" ::: "memory");
        __syncthreads();

        uint32_t Ab = dbase + (c & 1) * STAGE_BYTES;
        uint32_t Bq = Ab + A_BYTES;
        uint32_t rowa = (uint32_t)(wid * 16 + tg);
        uint32_t ra = Ab + rowa * 256 + 4 * tig;
        uint32_t rb = ra + 8 * 256;

#pragma unroll
        for (int s = 0; s < KCB / 16; s++) {          // 8 k-steps of 16
            uint32_t sw0 = (uint32_t)(((2 * s)     ^ tg) << 4);
            uint32_t sw1 = (uint32_t)(((2 * s + 1) ^ tg) << 4);
            uint32_t a0 = lds32(ra + sw0);
            uint32_t a2 = lds32(ra + sw1);
            uint32_t a1 = lds32(rb + sw0);
            uint32_t a3 = lds32(rb + sw1);
#pragma unroll
            for (int nt = 0; nt < 6; nt++) {
                uint32_t db = Bq + (uint32_t)(nt * 8 + tg) * 256 + 4 * tig;
                uint32_t b0 = lds32(db + sw0);
                uint32_t b1 = lds32(db + sw1);
                asm volatile(
                    "mma.sync.aligned.m16n8k16.row.col.f32.bf16.bf16.f32 "
                    "{%0,%1,%2,%3}, {%4,%5,%6,%7}, {%8,%9}, {%0,%1,%2,%3};"
                    : "+f"(acc[nt][0]), "+f"(acc[nt][1]),
                      "+f"(acc[nt][2]), "+f"(acc[nt][3])
                    : "r"(a0), "r"(a1), "r"(a2), "r"(a3),
                      "r"(b0), "r"(b1));
            }
        }
        __syncthreads();
        if (c + 2 < NCHH) stage(c & 1, c + 2);
    }

    // write partials (deterministic; merged by crf_ep)
    float* pb = g_part + (size_t)bid * MT * QR;
    int r = wid * 16 + tg;
#pragma unroll
    for (int nt = 0; nt < 6; nt++) {
        int col = nt * 8 + 2 * tig;
        *(float2*)(pb + (size_t)r * QR + col)       = make_float2(acc[nt][0], acc[nt][1]);
        *(float2*)(pb + (size_t)(r + 8) * QR + col) = make_float2(acc[nt][2], acc[nt][3]);
    }
}

// Merge k-split partials + fused epilogue (coalesced float4 loads through smem).
__global__ __launch_bounds__(256)
void crf_ep(const float* __restrict__ seg,
            const float* __restrict__ wts,
            float* __restrict__ out,
            int qsel, int last)
{
    __shared__ float w_s[DD * DD];
    __shared__ float sp[MT][QR + 1];     // pitch 49: conflict-free row reads
    int tid = threadIdx.x;
    int bid = blockIdx.x;            // BSZ*32 blocks
    int b = bid >> 5;
    int mtile = bid & 31;
    for (int i = tid; i < DD * DD; i += 256) w_s[i] = wts[i];

    const float* pb = g_part + (size_t)(bid * 2) * MT * QR;
#pragma unroll
    for (int i = tid; i < MT * QR / 4; i += 256) {    // 1536 float4s
        float4 v0 = *(const float4*)(pb + (size_t)i * 4);
        float4 v1 = *(const float4*)(pb + (size_t)MT * QR + (size_t)i * 4);
        int r = (i * 4) / QR;
        int c = (i * 4) % QR;                          // QR%4==0: same row
        sp[r][c]     = v0.x + v1.x;
        sp[r][c + 1] = v0.y + v1.y;
        sp[r][c + 2] = v0.z + v1.z;
        sp[r][c + 3] = v0.w + v1.w;
    }
    __syncthreads();

    if (tid < MT) {
        int m = mtile * MT + tid;
        float a2[DD + 1];
#pragma unroll
        for (int d = 0; d <= DD; d++) a2[d] = sp[tid][d] + sp[tid][24 + d];

        float rinv = 1.0f / a2[DD];       // rowsum via ones-row (col 21)
        float sd[DD];
#pragma unroll
        for (int e = 0; e < DD; e++) sd[e] = a2[e] * rinv;

        float o[DD];
#pragma unroll
        for (int d = 0; d < DD; d++) {
            float u = 0.f;
#pragma unroll
            for (int e = 0; e < DD; e++) u = fmaf(w_s[d * DD + e], sd[e], u);
            o[d] = seg[((size_t)(b * DD + d)) * NN + m] - u;
        }

        if (last) {
#pragma unroll
            for (int d = 0; d < DD; d++)
                out[((size_t)(b * DD + d)) * NN + m] = o[d];
        } else {
            float mx = -3.4e38f;
#pragma unroll
            for (int d = 0; d < DD; d++) mx = fmaxf(mx, o[d]);
            float ssum = 0.f;
            float ex[DD];
#pragma unroll
            for (int d = 0; d < DD; d++) { ex[d] = __expf(o[d] - mx); ssum += ex[d]; }
            float si = 1.0f / ssum;
            __nv_bfloat16* qo = (qsel ? g_QA : g_QB) + (size_t)b * QR * NN + m;
#pragma unroll
            for (int d = 0; d < DD; d++) {
                float q = ex[d] * si;
                __nv_bfloat16 hb = __float2bfloat16(q);
                qo[(size_t)d * NN] = hb;
                qo[(size_t)(24 + d) * NN] = __float2bfloat16(q - __bfloat162float(hb));
            }
        }
    }
}

extern "C" void kernel_launch(void* const* d_in, const int* in_sizes, int n_in,
                              void* d_out, int out_size)
{
    const float* seg = nullptr;
    const float* W   = nullptr;
    const float* wts = nullptr;
    for (int i = 0; i < n_in; i++) {
        if (in_sizes[i] == BSZ * DD * NN)       seg = (const float*)d_in[i];
        else if (in_sizes[i] == BSZ * NN * NN)  W   = (const float*)d_in[i];
        else if (in_sizes[i] == DD * DD)        wts = (const float*)d_in[i];
    }

    cudaFuncSetAttribute(crf_mma, cudaFuncAttributeMaxDynamicSharedMemorySize,
                         DSMEM_BYTES);
    cudaFuncSetAttribute(crf_mma_w0, cudaFuncAttributeMaxDynamicSharedMemorySize,
                         W0_DSMEM);

    softmax0_kernel<<<(BSZ * NN) / 256, 256>>>(seg);
    for (int it = 0; it < NITERS; it++) {
        if (it == 0)
            crf_mma_w0<<<BSZ * 64, THREADS, W0_DSMEM>>>(W);
        else
            crf_mma<<<BSZ * 64, THREADS, DSMEM_BYTES>>>(it & 1);
        crf_ep<<<BSZ * 32, 256>>>(seg, wts, (float*)d_out,
                                  it & 1, (it == NITERS - 1) ? 1 : 0);
    }
}